// round 16
// baseline (speedup 1.0000x reference)
#include <cuda_runtime.h>
#include <math.h>

#define B_DIM 64
#define C_DIM 80
#define T_DIM 16384
#define NTHREADS 256
#define NWARPS 8
#define NBIN 2048
#define CAP 4096
#define BINBUF 64
#define FULL 0xFFFFFFFFu

// fixed candidate windows around N(0,1) quartiles (immediates; exactness
// NEVER depends on them -- coverage is verified against the exact histogram)
#define W0LO (-0.7544898f)
#define W0HI (-0.5944898f)
#define W1LO (-0.08f)
#define W1HI (0.08f)
#define W2LO (0.5944898f)
#define W2HI (0.7544898f)

// order-preserving float <-> u32 key (exact total order incl. ties/-0)
__device__ __forceinline__ unsigned f2k(float f) {
    unsigned u = __float_as_uint(f);
    return u ^ ((unsigned)((int)u >> 31) | 0x80000000u);
}
__device__ __forceinline__ float k2f(unsigned k) {
    unsigned m = (k & 0x80000000u) ? 0x80000000u : 0xFFFFFFFFu;
    return __uint_as_float(k ^ m);
}

// value-linear bin: 2048 bins across [-4,4]; clamped; monotone
__device__ __forceinline__ int cbin(float f) {
    int bi = __float2int_rd(fmaf(f, 256.0f, 1024.0f));
    return max(0, min(NBIN - 1, bi));
}
__device__ __forceinline__ float binlo_val(int b2) {   // exact: 1/256 grid
    return (float)(b2 - 1024) * 0.00390625f;
}

__global__ void __launch_bounds__(NTHREADS, 8)
statpool_kernel(const float* __restrict__ x, const int* __restrict__ lengths,
                float* __restrict__ out) {
    extern __shared__ unsigned sh[];
    unsigned* hist = sh;                 // [2048] counts -> inclusive cumsum
    float* list = (float*)(sh + NBIN);   // [CAP] fixed-window candidates

    __shared__ float red_s[NWARPS], red_s2[NWARPS];
    __shared__ unsigned wtot[NWARPS], wbase[NWARPS];
    __shared__ int s_k[6];
    __shared__ float s_w[3];
    __shared__ int s_bin[6], s_krem[6], s_m[6];
    __shared__ int s_cnt;
    __shared__ int bcnt[6];
    __shared__ unsigned binbuf[6 * BINBUF];
    __shared__ unsigned s_keyout[6];

    const int row = blockIdx.x;
    const int b = row / C_DIM, c = row % C_DIM;
    const int n = lengths[b];
    const int tid = threadIdx.x, lane = tid & 31, warp = tid >> 5;

    for (int i = tid; i < NBIN; i += NTHREADS) hist[i] = 0u;
    if (tid < 6) bcnt[tid] = 0;
    if (tid == 0) s_cnt = 0;
    __syncthreads();

    // ---- SINGLE sweep: sums + histogram + fixed-window candidate capture ----
    const float* xrow = x + (size_t)row * T_DIM;
    const float4* x4 = (const float4*)xrow;
    const int nfull = n >> 2;
    float sum = 0.f, sumsq = 0.f;
    for (int i = tid; i < nfull; i += NTHREADS) {
        float4 v = x4[i];
        sum += v.x + v.y + v.z + v.w;
        sumsq = fmaf(v.x, v.x, sumsq); sumsq = fmaf(v.y, v.y, sumsq);
        sumsq = fmaf(v.z, v.z, sumsq); sumsq = fmaf(v.w, v.w, sumsq);
        atomicAdd(&hist[cbin(v.x)], 1u);
        atomicAdd(&hist[cbin(v.y)], 1u);
        atomicAdd(&hist[cbin(v.z)], 1u);
        atomicAdd(&hist[cbin(v.w)], 1u);
        bool d0 = ((v.x >= W0LO) & (v.x < W0HI)) | ((v.x >= W1LO) & (v.x < W1HI))
                | ((v.x >= W2LO) & (v.x < W2HI));
        bool d1 = ((v.y >= W0LO) & (v.y < W0HI)) | ((v.y >= W1LO) & (v.y < W1HI))
                | ((v.y >= W2LO) & (v.y < W2HI));
        bool d2 = ((v.z >= W0LO) & (v.z < W0HI)) | ((v.z >= W1LO) & (v.z < W1HI))
                | ((v.z >= W2LO) & (v.z < W2HI));
        bool d3 = ((v.w >= W0LO) & (v.w < W0HI)) | ((v.w >= W1LO) & (v.w < W1HI))
                | ((v.w >= W2LO) & (v.w < W2HI));
        int h = (int)d0 + (int)d1 + (int)d2 + (int)d3;
        if (h) {                          // one atomic covers up to 4 appends
            int p = atomicAdd(&s_cnt, h);
            if (d0) { if (p < CAP) list[p] = v.x; p++; }
            if (d1) { if (p < CAP) list[p] = v.y; p++; }
            if (d2) { if (p < CAP) list[p] = v.z; p++; }
            if (d3) { if (p < CAP) list[p] = v.w; p++; }
        }
    }
    if (tid == 0) {                       // tail: <=3 elements
        for (int t = nfull << 2; t < n; ++t) {
            float f = xrow[t];
            sum += f; sumsq = fmaf(f, f, sumsq);
            atomicAdd(&hist[cbin(f)], 1u);
            bool d = ((f >= W0LO) & (f < W0HI)) | ((f >= W1LO) & (f < W1HI))
                   | ((f >= W2LO) & (f < W2HI));
            if (d) { int p = atomicAdd(&s_cnt, 1); if (p < CAP) list[p] = f; }
        }
    }
#pragma unroll
    for (int o = 16; o; o >>= 1) {
        sum += __shfl_down_sync(FULL, sum, o);
        sumsq += __shfl_down_sync(FULL, sumsq, o);
    }
    if (lane == 0) { red_s[warp] = sum; red_s2[warp] = sumsq; }
    __syncthreads();

    // ---- inclusive scan of hist (8 bins/thread) ----
    unsigned vb[8], loc = 0;
#pragma unroll
    for (int d = 0; d < 8; ++d) { vb[d] = hist[tid * 8 + d]; loc += vb[d]; }
    unsigned inc = loc;
#pragma unroll
    for (int o = 1; o < 32; o <<= 1) {
        unsigned t = __shfl_up_sync(FULL, inc, o);
        if (lane >= o) inc += t;
    }
    if (lane == 31) wtot[warp] = inc;
    __syncthreads();

    if (warp == 0) {
        unsigned t = (lane < NWARPS) ? wtot[lane] : 0u;
        unsigned ti = t;
#pragma unroll
        for (int o = 1; o < NWARPS; o <<= 1) {
            unsigned u = __shfl_up_sync(FULL, ti, o);
            if (lane >= o) ti += u;
        }
        if (lane < NWARPS) wbase[lane] = ti - t;
    } else if (tid == 32) {
        // mean/std + rank targets (concurrent with warp 0's base scan)
        float s = 0.f, s2 = 0.f;
#pragma unroll
        for (int w = 0; w < NWARPS; ++w) { s += red_s[w]; s2 += red_s2[w]; }
        float fn = (float)n;
        float mean = s / fn;
        float var = fmaxf(s2 / fn - mean * mean, 1e-6f);
        out[b * (5 * C_DIM) + 0 * C_DIM + c] = mean;
        out[b * (5 * C_DIM) + 1 * C_DIM + c] = sqrtf(var);
        float n1 = (float)(n - 1);
        const float qs[3] = {0.25f, 0.5f, 0.75f};
#pragma unroll
        for (int q = 0; q < 3; ++q) {
            float pos = qs[q] * n1;
            float flo = floorf(pos);
            s_k[2 * q]     = (int)flo;
            s_k[2 * q + 1] = (int)ceilf(pos);
            s_w[q] = pos - flo;
        }
    }
    __syncthreads();

    unsigned run = wbase[warp] + (inc - loc);
#pragma unroll
    for (int d = 0; d < 8; ++d) { run += vb[d]; hist[tid * 8 + d] = run; }
    __syncthreads();

    // ---- locate target bins; exact below-counts & bin sizes from cumsum ----
    if (tid < 6) {
        int k = s_k[tid];
        int lo = 0, hi = NBIN - 1;
        while (lo < hi) {
            int mid = (lo + hi) >> 1;
            if ((int)hist[mid] > k) hi = mid; else lo = mid + 1;
        }
        int below = lo ? (int)hist[lo - 1] : 0;
        s_bin[tid] = lo;
        s_krem[tid] = k - below;
        s_m[tid] = (int)hist[lo] - below;
    }
    __syncthreads();

    const int cnt = min(s_cnt, CAP);
    const int ovf = (s_cnt > CAP);

    // ---- selection: warp j resolves target j ----
    if (warp < 6) {
        const int q = warp >> 1;
        const int B = s_bin[warp];
        const int mexp = s_m[warp];
        const int krem = s_krem[warp];
        const float wql = (q == 0) ? W0LO : ((q == 1) ? W1LO : W2LO);
        const float wqh = (q == 0) ? W0HI : ((q == 1) ? W1HI : W2HI);

        // coverage gate: bin B's exact value range must lie inside window q
        bool covered = (B > 0) && (B < NBIN - 1) &&
                       (binlo_val(B) >= wql) && (binlo_val(B + 1) <= wqh);
        bool need_fb = ovf || !covered || (mexp > BINBUF) ||
                       (krem < 0) || (krem >= mexp);

        if (!need_fb) {
            // collect exact members of bin B from the candidate list
            for (int i = lane; i < cnt; i += 32) {
                float f = list[i];
                if (cbin(f) == B) {
                    int p = atomicAdd(&bcnt[warp], 1);
                    if (p < BINBUF) binbuf[warp * BINBUF + p] = f2k(f);
                }
            }
            __syncwarp();
            if (bcnt[warp] != mexp) need_fb = true;   // verification gate
        }

        if (!need_fb) {
            // exact stable-rank among mexp (<=64) keys; uniform trips
            const unsigned* L = binbuf + warp * BINBUF;
            for (int base = 0; base < mexp; base += 32) {
                int idx = base + lane;
                unsigned e = (idx < mexp) ? L[idx] : 0xFFFFFFFFu;
                int cl = 0, ce = 0;
                for (int t = 0; t < mexp; ++t) {
                    unsigned o = L[t];              // broadcast read
                    cl += (o < e);
                    ce += (o == e && t < idx);
                }
                if (idx < mexp && cl + ce == krem) s_keyout[warp] = e;
            }
        } else {
            // exact fallback: 32-step key bisection over the full global row
            const int kglob = s_k[warp];
            unsigned prefix = 0u;
            for (int bit = 31; bit >= 0; --bit) {
                unsigned cand2 = prefix | (1u << bit);
                unsigned cc = 0;
                for (int i2 = lane; i2 < T_DIM; i2 += 32)
                    if (i2 < n) cc += (f2k(xrow[i2]) < cand2) ? 1u : 0u;
#pragma unroll
                for (int o = 16; o; o >>= 1) cc += __shfl_down_sync(FULL, cc, o);
                cc = __shfl_sync(FULL, cc, 0);
                if (cc <= (unsigned)kglob) prefix = cand2;
            }
            if (lane == 0) s_keyout[warp] = prefix;
        }
    }
    __syncthreads();

    // ---- quantile interpolation + writeback ----
    if (tid < 3) {
        float vlo = k2f(s_keyout[2 * tid]);
        float vhi = k2f(s_keyout[2 * tid + 1]);
        out[b * (5 * C_DIM) + (2 + tid) * C_DIM + c] = vlo + s_w[tid] * (vhi - vlo);
    }
}

extern "C" void kernel_launch(void* const* d_in, const int* in_sizes, int n_in,
                              void* d_out, int out_size) {
    const float* x;
    const int* lengths;
    if (in_sizes[0] == B_DIM) {
        lengths = (const int*)d_in[0];
        x = (const float*)d_in[1];
    } else {
        x = (const float*)d_in[0];
        lengths = (const int*)d_in[1];
    }
    float* out = (float*)d_out;

    // 8 KB hist + 16 KB list = 24 KB dynamic -> 8 CTAs/SM
    size_t smem = (size_t)(NBIN + CAP) * sizeof(unsigned);
    cudaFuncSetAttribute(statpool_kernel,
                         cudaFuncAttributeMaxDynamicSharedMemorySize, (int)smem);
    statpool_kernel<<<B_DIM * C_DIM, NTHREADS, smem>>>(x, lengths, out);
}